// round 14
// baseline (speedup 1.0000x reference)
#include <cuda_runtime.h>
#include <stdint.h>

#define BATCH 64
#define HH 1024
#define WW 1024
#define HWSZ (HH*WW)
#define NBINS 4096
#define CAP 4096
#define SSTAGE 2048              // shared staging (16 KB)
#define KMAX 256
#define NMS_R 0.05f
#define EPB 16384                // elements per collect block (4x bigger: amortize epilogue)
#define BPB 64                   // collect blocks per batch = HWSZ/EPB
#define THRESH 3.6f              // exact float threshold (R13-proven)

__device__ int g_count[BATCH];          // zero-init; self-reset each run
__device__ int g_done[BATCH];           // zero-init; self-reset each run
__device__ int g_hist[BATCH * NBINS];   // fallback only; zeroed in-path
__device__ unsigned long long g_cand[BATCH * CAP];

__device__ __forceinline__ unsigned int fkey(float x) {
    unsigned int u = __float_as_uint(x);
    return (u & 0x80000000u) ? ~u : (u | 0x80000000u);
}

// fallback emit: bin-threshold compare (exact top-K path)
__device__ __forceinline__ void emit_bin(float x, long long e, int b, unsigned int t12) {
    unsigned int kx = fkey(x);
    if ((kx >> 20) >= t12) {
        int s = atomicAdd(&g_count[b], 1);
        if (s < CAP) {
            unsigned int pos = (unsigned int)(e & (HWSZ - 1));
            g_cand[b * CAP + s] = ((unsigned long long)kx << 32) | (unsigned int)(~pos);
        }
    }
}

// fast-path emit: caller already compared; x >= THRESH > 0 here
__device__ __forceinline__ void emit_hit(float x, unsigned int pos, int b) {
    unsigned int kx = __float_as_uint(x) | 0x80000000u;
    int s = atomicAdd(&g_count[b], 1);
    if (s < CAP)
        g_cand[b * CAP + s] = ((unsigned long long)kx << 32) | (unsigned int)(~pos);
}

__global__ void __launch_bounds__(256) k_all(const float* __restrict__ hm,
                                             const int* __restrict__ ncp,
                                             float* __restrict__ out) {
    // ---------------- collect blocks (blockIdx >= BATCH) ----------------
    if (blockIdx.x >= BATCH) {
        const int cb = blockIdx.x - BATCH;
        const long long base = (long long)cb * EPB;
        const int b = (int)(base >> 20);
        const unsigned int inb = (unsigned int)(base & (HWSZ - 1));
        const float4* p = (const float4*)(hm + base);
#pragma unroll 4
        for (int it = 0; it < 16; it++) {
            int i = threadIdx.x + it * 256;
            float4 v = p[i];
            unsigned int pos = inb + 4u * i;
            if (v.x >= THRESH) emit_hit(v.x, pos + 0, b);
            if (v.y >= THRESH) emit_hit(v.y, pos + 1, b);
            if (v.z >= THRESH) emit_hit(v.z, pos + 2, b);
            if (v.w >= THRESH) emit_hit(v.w, pos + 3, b);
        }
        __syncthreads();                    // CTA-scope HB for all emits
        if (threadIdx.x == 0) {
            __threadfence();                // extend to GPU scope
            atomicAdd(&g_done[b], 1);
        }
        return;
    }

    // ---------------- finalize blocks (blockIdx < BATCH) ----------------
    const int b = blockIdx.x;
    __shared__ unsigned long long skey[SSTAGE];   // 16 KB
    __shared__ float2 co[KMAX];
    __shared__ unsigned long long adj[64];
    __shared__ int order[64];
    __shared__ int sh_sel;
    __shared__ unsigned int sh_t12;

    int nc = ncp ? *ncp : 16;
    int K = 4 * nc; if (K > KMAX) K = KMAX; if (K > HWSZ) K = HWSZ;

    // wait for this batch's collect blocks
    if (threadIdx.x == 0) {
        while (atomicAdd(&g_done[b], 0) < BPB) __nanosleep(128);
    }
    __syncthreads();
    __threadfence();                        // acquire: see collect blocks' writes

    int c = g_count[b];

    // ---- exact fallback if static threshold missed (global hist; cold path) ----
    if (c < K || c > CAP) {
        int* hist = &g_hist[b * NBINS];
        for (int i = threadIdx.x; i < NBINS; i += 256) hist[i] = 0;
        __syncthreads();
        const float4* p = (const float4*)(hm + (long long)b * HWSZ);
        for (int i = threadIdx.x; i < HWSZ / 4; i += 256) {
            float4 v = p[i];
            atomicAdd(&hist[fkey(v.x) >> 20], 1);
            atomicAdd(&hist[fkey(v.y) >> 20], 1);
            atomicAdd(&hist[fkey(v.z) >> 20], 1);
            atomicAdd(&hist[fkey(v.w) >> 20], 1);
        }
        __syncthreads();
        if (threadIdx.x == 0) {
            long long acc = 0; unsigned int t = 0;
            for (int i = NBINS - 1; i >= 0; i--) {
                acc += hist[i];
                if (acc >= K) { t = (unsigned int)i; break; }
            }
            sh_t12 = t;
            g_count[b] = 0;
        }
        __syncthreads();
        unsigned int t = sh_t12;
        for (int i = threadIdx.x; i < HWSZ / 4; i += 256) {
            float4 v = p[i];
            long long e = 4LL * i;
            emit_bin(v.x, e + 0, b, t);
            emit_bin(v.y, e + 1, b, t);
            emit_bin(v.z, e + 2, b, t);
            emit_bin(v.w, e + 3, b, t);
        }
        __syncthreads();
        c = g_count[b];
    }
    if (c > CAP) c = CAP;
    int Keff = (K < c) ? K : c;

    // ---- stage candidates in shared (up to SSTAGE; overflow read from L2) ----
    const unsigned long long* cand = &g_cand[b * CAP];
    int cs = (c < SSTAGE) ? c : SSTAGE;
    for (int i = threadIdx.x; i < cs; i += 256) skey[i] = cand[i];
    __syncthreads();

    // ---- rank selection: slot = #keys strictly greater (keys unique) ----
    for (int i = threadIdx.x; i < c; i += 256) {
        unsigned long long mk = (i < cs) ? skey[i] : cand[i];
        int rank = 0;
#pragma unroll 8
        for (int j = 0; j < cs; j++) rank += (skey[j] > mk) ? 1 : 0;
        for (int j = cs; j < c; j++) rank += (__ldg(&cand[j]) > mk) ? 1 : 0;
        if (rank < Keff) {
            unsigned int pos = ~(unsigned int)(mk & 0xFFFFFFFFULL);
            co[rank] = make_float2((float)(pos & (WW - 1)) / (float)(WW - 1),
                                   (float)(pos >> 10) / (float)(HH - 1));
        }
    }
    __syncthreads();

    // ---- greedy NMS ----
    int keep = (nc > 64) ? 64 : nc;
    if (Keff <= 64) {
        if (threadIdx.x < (unsigned)Keff) {
            int i = threadIdx.x;
            float x = co[i].x, y = co[i].y;
            unsigned long long m = 0;
            for (int j = 0; j < i; j++) {
                float dx = x - co[j].x, dy = y - co[j].y;
                if (sqrtf(dx * dx + dy * dy) < NMS_R) m |= (1ULL << j);
            }
            adj[i] = m;
        }
        __syncthreads();
        if (threadIdx.x == 0) {
            unsigned long long selmask = 0;
            int sel = 0;
#pragma unroll
            for (int i = 0; i < 64; i++) {
                bool ok = (i < Keff) && (sel < keep) && ((adj[i] & selmask) == 0);
                if (ok) {
                    selmask |= (1ULL << i);
                    order[sel] = i;
                    sel++;
                }
            }
            sh_sel = sel;
            g_count[b] = 0;                 // self-reset for next replay
            g_done[b] = 0;
        }
        __syncthreads();
        int sel = sh_sel;
        if (threadIdx.x < (unsigned)(2 * nc) && nc <= 128) {
            int s = threadIdx.x >> 1;
            int xy = threadIdx.x & 1;
            float val = 0.0f;
            if (s < sel) {
                float2 cc = co[order[s]];
                val = xy ? cc.y : cc.x;
            }
            out[((long long)b * nc + s) * 2 + xy] = val;
        } else if (threadIdx.x == 0 && nc > 128) {
            for (int s = 0; s < nc; s++) {
                float ox = 0.0f, oy = 0.0f;
                if (s < sel) { ox = co[order[s]].x; oy = co[order[s]].y; }
                out[((long long)b * nc + s) * 2 + 0] = ox;
                out[((long long)b * nc + s) * 2 + 1] = oy;
            }
        }
    } else {
        if (threadIdx.x == 0) {
            float sx[64], sy[64];
            int sel = 0;
            for (int i = 0; i < Keff && sel < keep; i++) {
                float x = co[i].x, y = co[i].y;
                bool close = false;
                for (int j = 0; j < sel; j++) {
                    float dx = x - sx[j], dy = y - sy[j];
                    if (sqrtf(dx * dx + dy * dy) < NMS_R) { close = true; break; }
                }
                if (!close) { sx[sel] = x; sy[sel] = y; sel++; }
            }
            for (int s = 0; s < nc; s++) {
                out[((long long)b * nc + s) * 2 + 0] = (s < sel) ? sx[s] : 0.0f;
                out[((long long)b * nc + s) * 2 + 1] = (s < sel) ? sy[s] : 0.0f;
            }
            g_count[b] = 0;
            g_done[b] = 0;
        }
    }
}

extern "C" void kernel_launch(void* const* d_in, const int* in_sizes, int n_in,
                              void* d_out, int out_size) {
    const float* hm = (const float*)d_in[0];
    const int* ncp = (n_in >= 2) ? (const int*)d_in[1] : nullptr;
    float* out = (float*)d_out;

    k_all<<<BATCH + BATCH * BPB, 256>>>(hm, ncp, out);
    (void)in_sizes; (void)out_size;
}

// round 15
// speedup vs baseline: 1.2079x; 1.2079x over previous
#include <cuda_runtime.h>
#include <stdint.h>

#define BATCH 64
#define HH 1024
#define WW 1024
#define HWSZ (HH*WW)
#define NBINS 4096
#define CAP 4096
#define KMAX 256
#define NMS_R 0.05f
#define THRESH 3.6f

__device__ int g_count[BATCH];                       // zero-init; self-reset each run
__device__ unsigned long long g_cand[BATCH * CAP];

__device__ __forceinline__ unsigned int fkey(float x) {
    unsigned int u = __float_as_uint(x);
    return (u & 0x80000000u) ? ~u : (u | 0x80000000u);
}

__device__ __forceinline__ void emit_bin(float x, long long e, int b, unsigned int t12) {
    unsigned int kx = fkey(x);
    if ((kx >> 20) >= t12) {
        int s = atomicAdd(&g_count[b], 1);
        if (s < CAP) {
            unsigned int pos = (unsigned int)(e & (HWSZ - 1));
            g_cand[b * CAP + s] = ((unsigned long long)kx << 32) | (unsigned int)(~pos);
        }
    }
}

__device__ __forceinline__ void emit_hit(float x, unsigned int pos, int b) {
    unsigned int kx = __float_as_uint(x) | 0x80000000u;   // fkey for positive floats
    int s = atomicAdd(&g_count[b], 1);
    if (s < CAP)
        g_cand[b * CAP + s] = ((unsigned long long)kx << 32) | (unsigned int)(~pos);
}

// pure streaming pass: single FSETP per element. (R13-proven, byte-identical)
__global__ void __launch_bounds__(256) k_collect_static(const float* __restrict__ hm) {
    const long long base = (long long)blockIdx.x * 4096;
    const int b = (int)(base >> 20);
    const unsigned int inb = (unsigned int)(base & (HWSZ - 1));
    const float4* p = (const float4*)(hm + base);
#pragma unroll
    for (int it = 0; it < 4; it++) {
        int i = threadIdx.x + it * 256;
        float4 v = p[i];
        unsigned int pos = inb + 4u * i;
        if (v.x >= THRESH) emit_hit(v.x, pos + 0, b);
        if (v.y >= THRESH) emit_hit(v.y, pos + 1, b);
        if (v.z >= THRESH) emit_hit(v.z, pos + 2, b);
        if (v.w >= THRESH) emit_hit(v.w, pos + 3, b);
    }
}

// per-batch finalize: speculative candidate load + rank selection + parallel NMS
__global__ void __launch_bounds__(256) k_finalize(const float* __restrict__ hm,
                                                  const int* __restrict__ ncp,
                                                  float* __restrict__ out) {
    const int b = blockIdx.x;
    __shared__ union {
        unsigned long long skey[CAP];
        int hist[NBINS];
    } u;
    __shared__ float2 co[KMAX];
    __shared__ unsigned long long adj[64];
    __shared__ int order[64];
    __shared__ int sh_sel;
    __shared__ unsigned int sh_t12;

    // all header loads independent, issued at cycle 0:
    const unsigned long long* cand = &g_cand[b * CAP];
    unsigned long long mykey = cand[threadIdx.x];   // speculative (CAP-sized buffer: in-bounds)
    int c = g_count[b];
    int nc = ncp ? *ncp : 16;
    int K = 4 * nc; if (K > KMAX) K = KMAX; if (K > HWSZ) K = HWSZ;

    // ---- exact fallback if static threshold missed ----
    if (c < K || c > CAP) {
        for (int i = threadIdx.x; i < NBINS; i += 256) u.hist[i] = 0;
        __syncthreads();
        const float4* p = (const float4*)(hm + (long long)b * HWSZ);
        for (int i = threadIdx.x; i < HWSZ / 4; i += 256) {
            float4 v = p[i];
            atomicAdd(&u.hist[fkey(v.x) >> 20], 1);
            atomicAdd(&u.hist[fkey(v.y) >> 20], 1);
            atomicAdd(&u.hist[fkey(v.z) >> 20], 1);
            atomicAdd(&u.hist[fkey(v.w) >> 20], 1);
        }
        __syncthreads();
        if (threadIdx.x == 0) {
            long long acc = 0; unsigned int t = 0;
            for (int i = NBINS - 1; i >= 0; i--) {
                acc += u.hist[i];
                if (acc >= K) { t = (unsigned int)i; break; }
            }
            sh_t12 = t;
            g_count[b] = 0;
        }
        __syncthreads();
        unsigned int t = sh_t12;
        for (int i = threadIdx.x; i < HWSZ / 4; i += 256) {
            float4 v = p[i];
            long long e = 4LL * i;
            emit_bin(v.x, e + 0, b, t);
            emit_bin(v.y, e + 1, b, t);
            emit_bin(v.z, e + 2, b, t);
            emit_bin(v.w, e + 3, b, t);
        }
        __syncthreads();
        c = g_count[b];
        if (c > CAP) c = CAP;
        mykey = cand[threadIdx.x];              // re-load after refill
        __syncthreads();                        // union hist -> skey reuse safety
    }
    int Keff = (K < c) ? K : c;

    // ---- rank selection ----
    if (c <= 256) {
        // fast path: thread i owns candidate i; single global round-trip already done
        u.skey[threadIdx.x] = mykey;
        __syncthreads();
        if (threadIdx.x < (unsigned)c) {
            int rank = 0;
            for (int j = 0; j < c; j++) rank += (u.skey[j] > mykey) ? 1 : 0;
            if (rank < Keff) {
                unsigned int pos = ~(unsigned int)(mykey & 0xFFFFFFFFULL);
                co[rank] = make_float2((float)(pos & (WW - 1)) / (float)(WW - 1),
                                       (float)(pos >> 10) / (float)(HH - 1));
            }
        }
    } else {
        // general path (c in (256, CAP])
        for (int i = threadIdx.x; i < c; i += 256) u.skey[i] = cand[i];
        __syncthreads();
        for (int i = threadIdx.x; i < c; i += 256) {
            unsigned long long mk = u.skey[i];
            int rank = 0;
#pragma unroll 8
            for (int j = 0; j < c; j++) rank += (u.skey[j] > mk) ? 1 : 0;
            if (rank < Keff) {
                unsigned int pos = ~(unsigned int)(mk & 0xFFFFFFFFULL);
                co[rank] = make_float2((float)(pos & (WW - 1)) / (float)(WW - 1),
                                       (float)(pos >> 10) / (float)(HH - 1));
            }
        }
    }
    __syncthreads();

    // ---- greedy NMS ----
    int keep = (nc > 64) ? 64 : nc;
    if (Keff <= 64) {
        if (threadIdx.x < (unsigned)Keff) {
            int i = threadIdx.x;
            float x = co[i].x, y = co[i].y;
            unsigned long long m = 0;
            for (int j = 0; j < i; j++) {
                float dx = x - co[j].x, dy = y - co[j].y;
                if (sqrtf(dx * dx + dy * dy) < NMS_R) m |= (1ULL << j);
            }
            adj[i] = m;
        }
        __syncthreads();
        if (threadIdx.x == 0) {
            unsigned long long selmask = 0;
            int sel = 0;
#pragma unroll
            for (int i = 0; i < 64; i++) {
                bool ok = (i < Keff) && (sel < keep) && ((adj[i] & selmask) == 0);
                if (ok) {
                    selmask |= (1ULL << i);
                    order[sel] = i;
                    sel++;
                }
            }
            sh_sel = sel;
            g_count[b] = 0;                  // self-reset for next replay
        }
        __syncthreads();
        int sel = sh_sel;
        if (threadIdx.x < (unsigned)(2 * nc) && nc <= 128) {
            int s = threadIdx.x >> 1;
            int xy = threadIdx.x & 1;
            float val = 0.0f;
            if (s < sel) {
                float2 cc = co[order[s]];
                val = xy ? cc.y : cc.x;
            }
            out[((long long)b * nc + s) * 2 + xy] = val;
        } else if (threadIdx.x == 0 && nc > 128) {
            for (int s = 0; s < nc; s++) {
                float ox = 0.0f, oy = 0.0f;
                if (s < sel) { ox = co[order[s]].x; oy = co[order[s]].y; }
                out[((long long)b * nc + s) * 2 + 0] = ox;
                out[((long long)b * nc + s) * 2 + 1] = oy;
            }
        }
    } else {
        if (threadIdx.x == 0) {
            float sx[64], sy[64];
            int sel = 0;
            for (int i = 0; i < Keff && sel < keep; i++) {
                float x = co[i].x, y = co[i].y;
                bool close = false;
                for (int j = 0; j < sel; j++) {
                    float dx = x - sx[j], dy = y - sy[j];
                    if (sqrtf(dx * dx + dy * dy) < NMS_R) { close = true; break; }
                }
                if (!close) { sx[sel] = x; sy[sel] = y; sel++; }
            }
            for (int s = 0; s < nc; s++) {
                out[((long long)b * nc + s) * 2 + 0] = (s < sel) ? sx[s] : 0.0f;
                out[((long long)b * nc + s) * 2 + 1] = (s < sel) ? sy[s] : 0.0f;
            }
            g_count[b] = 0;
        }
    }
}

extern "C" void kernel_launch(void* const* d_in, const int* in_sizes, int n_in,
                              void* d_out, int out_size) {
    const float* hm = (const float*)d_in[0];
    const int* ncp = (n_in >= 2) ? (const int*)d_in[1] : nullptr;
    float* out = (float*)d_out;

    k_collect_static<<<(BATCH * (long long)HWSZ) / 4096, 256>>>(hm);
    k_finalize<<<BATCH, 256>>>(hm, ncp, out);
    (void)in_sizes; (void)out_size;
}